// round 1
// baseline (speedup 1.0000x reference)
#include <cuda_runtime.h>

// Problem constants (fixed by the reference):
//   B=256, T=2048, I=2, H=128, 3H=384
#define BB 256
#define TT 2048
#define HH 128
#define GG 384   // 3*H
#define NTHREADS 384

__device__ int d_order[BB];

// Rank batch indices by descending length (LPT schedule). One block, 256 threads.
__global__ void order_kernel(const int* __restrict__ lengths) {
    int i = threadIdx.x;
    int li = lengths[i];
    int rank = 0;
    #pragma unroll 8
    for (int j = 0; j < BB; j++) {
        int lj = lengths[j];
        rank += (lj > li) || (lj == li && j < i);
    }
    d_order[rank] = i;
}

// ---- packed f32x2 helpers (FFMA2 path; ptxas won't auto-fuse from C++) ----
__device__ __forceinline__ unsigned long long fma2(unsigned long long a,
                                                   unsigned long long b,
                                                   unsigned long long c) {
    unsigned long long d;
    asm("fma.rn.f32x2 %0, %1, %2, %3;" : "=l"(d) : "l"(a), "l"(b), "l"(c));
    return d;
}
__device__ __forceinline__ unsigned long long pack2(float x, float y) {
    unsigned long long r;
    asm("mov.b64 %0, {%1, %2};" : "=l"(r) : "f"(x), "f"(y));
    return r;
}
__device__ __forceinline__ void unpack2(unsigned long long v, float& x, float& y) {
    asm("mov.b64 {%0, %1}, %2;" : "=f"(x), "=f"(y) : "l"(v));
}

__device__ __forceinline__ float sigmoidf_acc(float v) {
    return 1.0f / (1.0f + expf(-v));
}

__global__ void __launch_bounds__(NTHREADS, 1)
gru_kernel(const float* __restrict__ x,        // [B, T, 2]
           const int*   __restrict__ lengths,  // [B]
           const float* __restrict__ W_ih,     // [384, 2]
           const float* __restrict__ W_hh,     // [384, 128]
           const float* __restrict__ b_ih,     // [384]
           const float* __restrict__ b_hh,     // [384]
           const float* __restrict__ head_w,   // [128]
           const float* __restrict__ head_b,   // [1]
           float*       __restrict__ out)      // [B, 1]
{
    __shared__ __align__(16) float sh_x[TT * 2];   // full input sequence: 16 KB
    __shared__ __align__(16) float sh_h[HH];       // hidden state
    __shared__ float sh_g[2 * HH];                 // z/n partial gates from threads 128..383

    const int tid = threadIdx.x;
    const int b = d_order[blockIdx.x];
    const int len = lengths[b];

    // --- load this sequence's inputs into shared (only the needed prefix) ---
    {
        const float4* xs = reinterpret_cast<const float4*>(x + (size_t)b * (TT * 2));
        float4* xd = reinterpret_cast<float4*>(sh_x);
        int nq = (len * 2 + 3) >> 2;
        for (int q = tid; q < nq; q += NTHREADS) xd[q] = xs[q];
    }

    // --- load W_hh row `tid` into 64 packed f32x2 registers ---
    unsigned long long w[64];
    {
        const unsigned long long* wrow =
            reinterpret_cast<const unsigned long long*>(W_hh + (size_t)tid * HH);
        #pragma unroll
        for (int t = 0; t < 64; t++) w[t] = wrow[t];
    }
    const float bhh = b_hh[tid];

    // --- per-thread gate constants for the combiner threads (tid < 128) ---
    float wr0 = 0.f, wr1 = 0.f, wz0 = 0.f, wz1 = 0.f, wn0 = 0.f, wn1 = 0.f;
    float br = 0.f, bz = 0.f, bn = 0.f;
    float h = 0.0f;
    float hw = 0.0f;
    if (tid < HH) {
        float2 t2;
        t2 = *reinterpret_cast<const float2*>(W_ih + (size_t)tid * 2);
        wr0 = t2.x; wr1 = t2.y;
        t2 = *reinterpret_cast<const float2*>(W_ih + (size_t)(HH + tid) * 2);
        wz0 = t2.x; wz1 = t2.y;
        t2 = *reinterpret_cast<const float2*>(W_ih + (size_t)(2 * HH + tid) * 2);
        wn0 = t2.x; wn1 = t2.y;
        br = b_ih[tid];
        bz = b_ih[HH + tid];
        bn = b_ih[2 * HH + tid];
        sh_h[tid] = 0.0f;
        hw = head_w[tid];
    }
    __syncthreads();

    // --- recurrence ---
    for (int t = 0; t < len; t++) {
        // gh[tid] = b_hh[tid] + sum_k W_hh[tid][k] * h[k], via packed f32x2 FMA
        unsigned long long acc0 = pack2(bhh, 0.0f);
        unsigned long long acc1 = pack2(0.0f, 0.0f);
        const ulonglong2* h2 = reinterpret_cast<const ulonglong2*>(sh_h);
        #pragma unroll
        for (int k = 0; k < 32; k++) {
            ulonglong2 hv = h2[k];             // LDS.128 broadcast
            acc0 = fma2(w[2 * k], hv.x, acc0);
            acc1 = fma2(w[2 * k + 1], hv.y, acc1);
        }
        float a0x, a0y, a1x, a1y;
        unpack2(acc0, a0x, a0y);
        unpack2(acc1, a1x, a1y);
        float gh = (a0x + a0y) + (a1x + a1y);

        if (tid >= HH) sh_g[tid - HH] = gh;   // z and n partials to shared
        __syncthreads();

        if (tid < HH) {
            float x0 = sh_x[2 * t];
            float x1 = sh_x[2 * t + 1];
            float hr = gh;                    // own row is the r-gate
            float hz = sh_g[tid];
            float hn = sh_g[HH + tid];
            float r = sigmoidf_acc(fmaf(wr0, x0, fmaf(wr1, x1, br)) + hr);
            float z = sigmoidf_acc(fmaf(wz0, x0, fmaf(wz1, x1, bz)) + hz);
            float n = tanhf(fmaf(wn0, x0, fmaf(wn1, x1, bn)) + r * hn);
            h = (1.0f - z) * n + z * h;
            sh_h[tid] = h;
        }
        __syncthreads();
    }

    // --- head: out[b] = sum_j h[j]*head_w[j] + head_b ---
    float v = (tid < HH) ? h * hw : 0.0f;
    #pragma unroll
    for (int o = 16; o > 0; o >>= 1) v += __shfl_down_sync(0xffffffffu, v, o);
    if ((tid & 31) == 0) sh_g[tid >> 5] = v;   // 12 warps (warps 4..11 contribute 0)
    __syncthreads();
    if (tid == 0) {
        float s = 0.0f;
        #pragma unroll
        for (int wi = 0; wi < NTHREADS / 32; wi++) s += sh_g[wi];
        out[b] = s + head_b[0];
    }
}

extern "C" void kernel_launch(void* const* d_in, const int* in_sizes, int n_in,
                              void* d_out, int out_size) {
    const float* x      = (const float*)d_in[0];
    const int*   len    = (const int*)  d_in[1];
    const float* W_ih   = (const float*)d_in[2];
    const float* W_hh   = (const float*)d_in[3];
    const float* b_ih   = (const float*)d_in[4];
    const float* b_hh   = (const float*)d_in[5];
    const float* head_w = (const float*)d_in[6];
    const float* head_b = (const float*)d_in[7];
    float* out = (float*)d_out;

    order_kernel<<<1, BB>>>(len);
    gru_kernel<<<BB, NTHREADS>>>(x, len, W_ih, W_hh, b_ih, b_hh,
                                 head_w, head_b, out);
}

// round 2
// speedup vs baseline: 1.0935x; 1.0935x over previous
#include <cuda_runtime.h>

// Problem constants (fixed by the reference):
//   B=256, T=2048, I=2, H=128, 3H=384
#define BB 256
#define TT 2048
#define HH 128
#define NTHREADS 384

__device__ int d_order[BB];

// Rank batch indices by descending length (LPT schedule). One block, 256 threads.
__global__ void order_kernel(const int* __restrict__ lengths) {
    int i = threadIdx.x;
    int li = lengths[i];
    int rank = 0;
    #pragma unroll 8
    for (int j = 0; j < BB; j++) {
        int lj = lengths[j];
        rank += (lj > li) || (lj == li && j < i);
    }
    d_order[rank] = i;
}

// ---- packed f32x2 helpers (FFMA2 path; ptxas won't auto-fuse from C++) ----
__device__ __forceinline__ unsigned long long fma2(unsigned long long a,
                                                   unsigned long long b,
                                                   unsigned long long c) {
    unsigned long long d;
    asm("fma.rn.f32x2 %0, %1, %2, %3;" : "=l"(d) : "l"(a), "l"(b), "l"(c));
    return d;
}
__device__ __forceinline__ unsigned long long pack2(float x, float y) {
    unsigned long long r;
    asm("mov.b64 %0, {%1, %2};" : "=l"(r) : "f"(x), "f"(y));
    return r;
}
__device__ __forceinline__ void unpack2(unsigned long long v, float& x, float& y) {
    asm("mov.b64 {%0, %1}, %2;" : "=f"(x), "=f"(y) : "l"(v));
}

// Fast sigmoid: MUFU.EX2-based __expf (~2 ulp) + MUFU.RCP divide (~2 ulp).
// Error ~1e-6 per call; safe against 1e-3 output tolerance even with
// 1/(1-z) ~ 10x recurrent amplification.
__device__ __forceinline__ float fsigmoid(float v) {
    float e = __expf(-v);
    return __fdividef(1.0f, 1.0f + e);
}
// Fast tanh: 1 - 2/(exp(2x)+1). Correct saturation at +/-inf and overflow.
__device__ __forceinline__ float ftanh(float v) {
    float e = __expf(2.0f * v);
    return 1.0f - __fdividef(2.0f, e + 1.0f);
}

__global__ void __launch_bounds__(NTHREADS, 1)
gru_kernel(const float* __restrict__ x,        // [B, T, 2]
           const int*   __restrict__ lengths,  // [B]
           const float* __restrict__ W_ih,     // [384, 2]
           const float* __restrict__ W_hh,     // [384, 128]
           const float* __restrict__ b_ih,     // [384]
           const float* __restrict__ b_hh,     // [384]
           const float* __restrict__ head_w,   // [128]
           const float* __restrict__ head_b,   // [1]
           float*       __restrict__ out)      // [B, 1]
{
    __shared__ __align__(16) float sh_x[TT * 2];   // full input sequence: 16 KB
    __shared__ __align__(16) float sh_h[HH];       // hidden state
    __shared__ float sh_g[2 * HH];                 // z/n partial gates

    const int tid = threadIdx.x;
    const int b = d_order[blockIdx.x];
    const int len = lengths[b];

    // --- load this sequence's inputs into shared (only the needed prefix) ---
    {
        const float4* xs = reinterpret_cast<const float4*>(x + (size_t)b * (TT * 2));
        float4* xd = reinterpret_cast<float4*>(sh_x);
        int nq = (len * 2 + 3) >> 2;
        for (int q = tid; q < nq; q += NTHREADS) xd[q] = xs[q];
    }

    // --- load W_hh row `tid` into 64 packed f32x2 registers ---
    unsigned long long w[64];
    {
        const unsigned long long* wrow =
            reinterpret_cast<const unsigned long long*>(W_hh + (size_t)tid * HH);
        #pragma unroll
        for (int t = 0; t < 64; t++) w[t] = wrow[t];
    }
    const float bhh = b_hh[tid];

    // --- per-thread gate constants for the combiner threads (tid < 128) ---
    float wr0 = 0.f, wr1 = 0.f, wz0 = 0.f, wz1 = 0.f, wn0 = 0.f, wn1 = 0.f;
    float br = 0.f, bz = 0.f, bn = 0.f;
    float h = 0.0f;
    float hw = 0.0f;
    if (tid < HH) {
        float2 t2;
        t2 = *reinterpret_cast<const float2*>(W_ih + (size_t)tid * 2);
        wr0 = t2.x; wr1 = t2.y;
        t2 = *reinterpret_cast<const float2*>(W_ih + (size_t)(HH + tid) * 2);
        wz0 = t2.x; wz1 = t2.y;
        t2 = *reinterpret_cast<const float2*>(W_ih + (size_t)(2 * HH + tid) * 2);
        wn0 = t2.x; wn1 = t2.y;
        br = b_ih[tid];
        bz = b_ih[HH + tid];
        bn = b_ih[2 * HH + tid];
        sh_h[tid] = 0.0f;
        hw = head_w[tid];
    }
    __syncthreads();

    // --- recurrence ---
    for (int t = 0; t < len; t++) {
        // Hoist the (h-independent) x(t) read so its LDS latency overlaps
        // the matvec instead of sitting on the gate-phase critical path.
        float x0 = 0.f, x1 = 0.f;
        if (tid < HH) {
            float2 xt = *reinterpret_cast<const float2*>(sh_x + 2 * t);
            x0 = xt.x; x1 = xt.y;
        }

        // gh[tid] = b_hh[tid] + sum_k W_hh[tid][k] * h[k]
        // 4 independent FMA2 chains (lat 4 / rt 2 needs >=2; 4 gives slack
        // for ptxas to hoist the LDS.128 broadcasts).
        unsigned long long acc0 = pack2(bhh, 0.0f);
        unsigned long long acc1 = pack2(0.0f, 0.0f);
        unsigned long long acc2 = acc1, acc3 = acc1;
        const ulonglong2* h2 = reinterpret_cast<const ulonglong2*>(sh_h);
        #pragma unroll
        for (int k = 0; k < 16; k++) {
            ulonglong2 ha = h2[2 * k];
            ulonglong2 hb = h2[2 * k + 1];
            acc0 = fma2(w[4 * k + 0], ha.x, acc0);
            acc1 = fma2(w[4 * k + 1], ha.y, acc1);
            acc2 = fma2(w[4 * k + 2], hb.x, acc2);
            acc3 = fma2(w[4 * k + 3], hb.y, acc3);
        }
        float a0x, a0y, a1x, a1y, a2x, a2y, a3x, a3y;
        unpack2(acc0, a0x, a0y);
        unpack2(acc1, a1x, a1y);
        unpack2(acc2, a2x, a2y);
        unpack2(acc3, a3x, a3y);
        float gh = ((a0x + a0y) + (a1x + a1y)) + ((a2x + a2y) + (a3x + a3y));

        if (tid >= HH) sh_g[tid - HH] = gh;   // z and n partials to shared
        __syncthreads();

        if (tid < HH) {
            float hr = gh;                    // own row is the r-gate
            float hz = sh_g[tid];
            float hn = sh_g[HH + tid];
            float r = fsigmoid(fmaf(wr0, x0, fmaf(wr1, x1, br)) + hr);
            float z = fsigmoid(fmaf(wz0, x0, fmaf(wz1, x1, bz)) + hz);
            float n = ftanh(fmaf(wn0, x0, fmaf(wn1, x1, bn)) + r * hn);
            h = fmaf(z, h - n, n);            // (1-z)*n + z*h
            sh_h[tid] = h;
        }
        __syncthreads();
    }

    // --- head: out[b] = sum_j h[j]*head_w[j] + head_b ---
    float v = (tid < HH) ? h * hw : 0.0f;
    #pragma unroll
    for (int o = 16; o > 0; o >>= 1) v += __shfl_down_sync(0xffffffffu, v, o);
    if ((tid & 31) == 0) sh_g[tid >> 5] = v;
    __syncthreads();
    if (tid == 0) {
        float s = 0.0f;
        #pragma unroll
        for (int wi = 0; wi < NTHREADS / 32; wi++) s += sh_g[wi];
        out[b] = s + head_b[0];
    }
}

extern "C" void kernel_launch(void* const* d_in, const int* in_sizes, int n_in,
                              void* d_out, int out_size) {
    const float* x      = (const float*)d_in[0];
    const int*   len    = (const int*)  d_in[1];
    const float* W_ih   = (const float*)d_in[2];
    const float* W_hh   = (const float*)d_in[3];
    const float* b_ih   = (const float*)d_in[4];
    const float* b_hh   = (const float*)d_in[5];
    const float* head_w = (const float*)d_in[6];
    const float* head_b = (const float*)d_in[7];
    float* out = (float*)d_out;

    order_kernel<<<1, BB>>>(len);
    gru_kernel<<<BB, NTHREADS>>>(x, len, W_ih, W_hh, b_ih, b_hh,
                                 head_w, head_b, out);
}